// round 17
// baseline (speedup 1.0000x reference)
#include <cuda_runtime.h>
#include <math.h>

#define NUM_RADIUS 15
#define NUM_ANGLE 48
#define EMB 32
#define NUM_ACTIONS 4
#define TPB 256
#define ROWS_PER_BLOCK (TPB * 4)   // 1024

// LR[r]  = (float4) logit contribution of radius bucket r
// LA[t]  = (float4) logit contribution of angle bucket t (+ bias)
// ELR[r] = exp(LR[r]) componentwise;  ELA[t] = exp(LA[t]) componentwise
__device__ float4 g_LR4[NUM_RADIUS];
__device__ float4 g_LA4[NUM_ANGLE];
__device__ float4 g_ELR4[NUM_RADIUS];
__device__ float4 g_ELA4[NUM_ANGLE];

// Warp-per-output precompute: 252 outputs, one warp each (32 blocks x 8 warps).
__global__ void __launch_bounds__(TPB)
precompute_tables_kernel(const float* __restrict__ radius_table,
                         const float* __restrict__ angle_table,
                         const float* __restrict__ W,
                         const float* __restrict__ b) {
    int warp = (blockIdx.x * TPB + threadIdx.x) >> 5;   // 0..255
    int lane = threadIdx.x & 31;
    const int NLR = NUM_RADIUS * NUM_ACTIONS;   // 60
    const int NLA = NUM_ANGLE * NUM_ACTIONS;    // 192

    float v = 0.0f;
    bool is_lr = warp < NLR;
    bool is_la = !is_lr && warp < NLR + NLA;
    if (is_lr) {
        int row = warp >> 2, a = warp & 3;
        v = radius_table[row * EMB + lane] * W[lane * NUM_ACTIONS + a];
    } else if (is_la) {
        int k = warp - NLR;
        int row = k >> 2, a = k & 3;
        v = angle_table[row * EMB + lane] * W[(EMB + lane) * NUM_ACTIONS + a];
        if (lane == 0) v += b[a];
    }
    #pragma unroll
    for (int off = 16; off > 0; off >>= 1)
        v += __shfl_down_sync(0xffffffffu, v, off);

    if (lane == 0) {
        if (is_lr) {
            ((float*)g_LR4)[warp] = v;
            ((float*)g_ELR4)[warp] = expf(v);    // accurate, one-time
        } else if (is_la) {
            ((float*)g_LA4)[warp - NLR] = v;
            ((float*)g_ELA4)[warp - NLR] = expf(v);
        }
    }
}

// Per-row pipeline. Fused atan2 (reuses radius for half-angle reduction:
// u = mn/(mx+radius), Taylor through u^13, err ~1e-6 rad). Softmax uses
// factored exponentials: exp(lr+la) = exp(lr)*exp(la) from tables, so the
// only MUFUs are sqrt, rcp, lg2 (3/row instead of 7).
__device__ __forceinline__ float4 process_row(float axp, float azp, float pose,
                                              float gx, float gz,
                                              const float4* __restrict__ sLR4,
                                              const float4* __restrict__ sLA4,
                                              const float4* __restrict__ sELR4,
                                              const float4* __restrict__ sELA4) {
    float dx = gx - axp;
    float dz = gz - azp;

    // radius bucket: max radius = sqrt(2)*50 ~ 70.7 < 75 -> r_idx <= 14
    float radius = sqrtf(fmaf(dx, dx, dz * dz));
    int r_idx = (int)(radius * 0.2f);

    float ax = fabsf(dx), ay = fabsf(dz);
    float mn = fminf(ax, ay), mx = fmaxf(ax, ay);
    float u = __fdividef(mn, mx + radius);
    float s = u * u;
    float p = 0.07692307693f;                 //  1/13
    p = fmaf(p, s, -0.09090909091f);          // -1/11
    p = fmaf(p, s,  0.11111111111f);          //  1/9
    p = fmaf(p, s, -0.14285714286f);          // -1/7
    p = fmaf(p, s,  0.2f);                    //  1/5
    p = fmaf(p, s, -0.33333333333f);          // -1/3
    float atu = fmaf(p * s, u, u);            // atan(u)
    float a = 2.0f * atu;                     // atan(mn/mx)
    if (ay > ax) a = 1.57079632679f - a;
    if (dx < 0.0f) a = 3.14159265359f - a;
    a = (dz < 0.0f) ? -a : a;                 // atan2(dz, dx)

    // angle bucket: match reference rounding (separate mul then subs)
    float deg = __fmul_rn(a, 57.29577951308232f);
    float dtg = __fsub_rn(90.0f, deg);
    float f = __fsub_rn(dtg, pose);
    float ad = fmaf(-360.0f, floorf(f * 0.0027777778f), f);
    ad = fminf(fmaxf(ad, 0.0f), 359.99997f);  // forces t_idx in [0,47]
    int t_idx = (int)(ad * 0.13333334f);

    float4 lr = sLR4[r_idx];
    float4 la = sLA4[t_idx];
    float4 er = sELR4[r_idx];
    float4 ea = sELA4[t_idx];

    float l0 = lr.x + la.x;
    float l1 = lr.y + la.y;
    float l2 = lr.z + la.z;
    float l3 = lr.w + la.w;

    // sum of exps via table products (exact to ulp vs exp(l_i))
    float sum = fmaf(er.x, ea.x, er.y * ea.y) + fmaf(er.z, ea.z, er.w * ea.w);
    float lse = __logf(sum);

    return make_float4(l0 - lse, l1 - lse, l2 - lse, l3 - lse);
}

// Coalesced mapping: block owns rows [R, R+1024); thread t handles rows
// R+t, R+256+t, R+512+t, R+768+t. goal LDG.64 and out STG.128 are
// lane-contiguous. Full blocks (99.95%) take an unpredicated fast path.
__global__ void __launch_bounds__(TPB, 8)
goal_position_kernel(const float* __restrict__ agentF,   // [B*3]
                     const float2* __restrict__ goal2,   // [B]
                     float4* __restrict__ out,           // [B]
                     int n) {                             // B
    __shared__ float4 sLR4[NUM_RADIUS];
    __shared__ float4 sLA4[NUM_ANGLE];
    __shared__ float4 sELR4[NUM_RADIUS];
    __shared__ float4 sELA4[NUM_ANGLE];
    int t = threadIdx.x;
    if (t < NUM_RADIUS) { sLR4[t] = g_LR4[t]; sELR4[t] = g_ELR4[t]; }
    if (t < NUM_ANGLE)  { sLA4[t] = g_LA4[t]; sELA4[t] = g_ELA4[t]; }
    __syncthreads();

    int R = blockIdx.x * ROWS_PER_BLOCK;
    int r0 = R + t;
    int r1 = r0 + TPB;
    int r2 = r1 + TPB;
    int r3 = r2 + TPB;

    if (R + ROWS_PER_BLOCK <= n) {
        // ---- fast path: no bounds checks ----
        float x0 = agentF[3*r0], z0 = agentF[3*r0+1], p0 = agentF[3*r0+2];
        float x1 = agentF[3*r1], z1 = agentF[3*r1+1], p1 = agentF[3*r1+2];
        float x2 = agentF[3*r2], z2 = agentF[3*r2+1], p2 = agentF[3*r2+2];
        float x3 = agentF[3*r3], z3 = agentF[3*r3+1], p3 = agentF[3*r3+2];
        float2 g0 = goal2[r0], g1 = goal2[r1], g2 = goal2[r2], g3 = goal2[r3];

        float4 o0 = process_row(x0, z0, p0, g0.x, g0.y, sLR4, sLA4, sELR4, sELA4);
        float4 o1 = process_row(x1, z1, p1, g1.x, g1.y, sLR4, sLA4, sELR4, sELA4);
        float4 o2 = process_row(x2, z2, p2, g2.x, g2.y, sLR4, sLA4, sELR4, sELA4);
        float4 o3 = process_row(x3, z3, p3, g3.x, g3.y, sLR4, sLA4, sELR4, sELA4);

        out[r0] = o0;
        out[r1] = o1;
        out[r2] = o2;
        out[r3] = o3;
    } else {
        // ---- tail path: guarded (last block only) ----
        #pragma unroll
        for (int k = 0; k < 4; k++) {
            int r = R + k * TPB + t;
            if (r < n) {
                float x = agentF[3*r], z = agentF[3*r+1], pz = agentF[3*r+2];
                float2 g = goal2[r];
                out[r] = process_row(x, z, pz, g.x, g.y, sLR4, sLA4, sELR4, sELA4);
            }
        }
    }
}

extern "C" void kernel_launch(void* const* d_in, const int* in_sizes, int n_in,
                              void* d_out, int out_size) {
    const float* agent = (const float*)d_in[0];   // [B,3]
    const float* goal = (const float*)d_in[1];    // [B,2]
    const float* radius_table = (const float*)d_in[2];
    const float* angle_table = (const float*)d_in[3];
    const float* W = (const float*)d_in[4];
    const float* b = (const float*)d_in[5];

    int n = in_sizes[0] / 3;    // B = 2,000,000

    precompute_tables_kernel<<<32, TPB>>>(radius_table, angle_table, W, b);

    int blocks = (n + ROWS_PER_BLOCK - 1) / ROWS_PER_BLOCK;   // 1954
    goal_position_kernel<<<blocks, TPB>>>(agent,
                                          (const float2*)goal,
                                          (float4*)d_out, n);
}